// round 4
// baseline (speedup 1.0000x reference)
#include <cuda_runtime.h>
#include <math.h>

#define NB_ALL 128
#define NB_S    64
#define NT     256
#define ROWS_B   8
#define ROWS_S  16
#define NN    1024
#define CC      64
#define NITERS  20
#define LSCALE 0.001f
#define NSLOT   48

// ---------------- device globals (no cudaMalloc allowed) ----------------
__device__ float g_psT[CC * NN];   // transposed softmax of y_s[7]  [C][N]
__device__ float g_ptT[CC * NN];   // transposed softmax of y_t[7]  [C][N]
__device__ float g_W[NN * NN];
__device__ float g_K[NN * NN];
__device__ float g_u[NN];
__device__ float g_v[NN];
__device__ float g_partial[NB_S];
// tree-barrier state: zero-init, self-resetting, generation flags monotonic
__device__ unsigned g_cnt1[NSLOT * 8 * 64];  // [slot][group], 256B stride
__device__ unsigned g_cnt2[NSLOT * 64];      // [slot] root counter, 256B stride
__device__ unsigned g_flagA[NSLOT];          // generation flags

// ---------------- reductions ----------------
__device__ __forceinline__ float warp_sum(float v) {
#pragma unroll
    for (int o = 16; o > 0; o >>= 1) v += __shfl_down_sync(0xffffffffu, v, o);
    return v;
}
__device__ __forceinline__ float warp_max(float v) {
#pragma unroll
    for (int o = 16; o > 0; o >>= 1) v = fmaxf(v, __shfl_down_sync(0xffffffffu, v, o));
    return v;
}
__device__ float block_sum(float v, float* sc) {
    int t = threadIdx.x;
    v = warp_sum(v);
    if ((t & 31) == 0) sc[t >> 5] = v;
    __syncthreads();
    if (t == 0) {
        float r = 0.f;
#pragma unroll
        for (int i = 0; i < 8; i++) r += sc[i];
        sc[8] = r;
    }
    __syncthreads();
    float r = sc[8];
    __syncthreads();
    return r;
}
__device__ float block_max(float v, float* sc) {
    int t = threadIdx.x;
    v = warp_max(v);
    if ((t & 31) == 0) sc[t >> 5] = v;
    __syncthreads();
    if (t == 0) {
        float r = -3.4e38f;
#pragma unroll
        for (int i = 0; i < 8; i++) r = fmaxf(r, sc[i]);
        sc[8] = r;
    }
    __syncthreads();
    float r = sc[8];
    __syncthreads();
    return r;
}

// ---------------- two-level tree grid barrier (gpu scope) ----------------
// 8 groups of gsz blocks each. Group counters live 256B apart so arrivals
// serialize only within a group (L2 atomic ALU is per-address). Root counter
// fans in the 8 group-leaders; the last one publishes generation R+1 with
// release; everyone else polls with acquire (invalidates stale L1).
__device__ __forceinline__ void gbar(int k, unsigned R, int b, int gsz) {
    __syncthreads();
    if (threadIdx.x == 0) {
        unsigned* c1 = &g_cnt1[((unsigned)k * 8u + (unsigned)(b / gsz)) * 64u];
        unsigned* c2 = &g_cnt2[(unsigned)k * 64u];
        unsigned* fl = &g_flagA[k];
        unsigned one = 1u, zero = 0u, old;
        asm volatile("atom.acq_rel.gpu.global.add.u32 %0, [%1], %2;"
                     : "=r"(old) : "l"(c1), "r"(one) : "memory");
        bool done = false;
        if (old == (unsigned)(gsz - 1)) {
            asm volatile("st.relaxed.gpu.global.u32 [%0], %1;"
                         :: "l"(c1), "r"(zero) : "memory");
            unsigned old2;
            asm volatile("atom.acq_rel.gpu.global.add.u32 %0, [%1], %2;"
                         : "=r"(old2) : "l"(c2), "r"(one) : "memory");
            if (old2 == 7u) {
                asm volatile("st.relaxed.gpu.global.u32 [%0], %1;"
                             :: "l"(c2), "r"(zero) : "memory");
                asm volatile("st.release.gpu.global.u32 [%0], %1;"
                             :: "l"(fl), "r"(R + 1u) : "memory");
                done = true;
            }
        }
        if (!done) {
            unsigned v;
            do {
                asm volatile("ld.acquire.gpu.global.u32 %0, [%1];"
                             : "=r"(v) : "l"(fl) : "memory");
            } while (v != R + 1u);
        }
    }
    __syncthreads();
}

// Sinkhorn half-step: rows 2w,2w+1 of Krows dotted with gin; gout = 1/dot.
__device__ __forceinline__ void halfstep(const float* __restrict__ Krows,
                                         const float* __restrict__ gin,
                                         float* __restrict__ gout,
                                         int i0, float* sVec, int t) {
    ((float4*)sVec)[t] = ((const float4*)gin)[t];
    __syncthreads();
    int w = t >> 5, l = t & 31;
    const float* K0 = Krows + (2 * w) * NN;
    const float* K1 = K0 + NN;
    float s0 = 0.f, s1 = 0.f;
#pragma unroll
    for (int k = 0; k < 8; k++) {
        int j = (l + k * 32) * 4;
        float4 vv = *(const float4*)&sVec[j];
        float4 a  = *(const float4*)&K0[j];
        float4 c  = *(const float4*)&K1[j];
        s0 += a.x * vv.x + a.y * vv.y + a.z * vv.z + a.w * vv.w;
        s1 += c.x * vv.x + c.y * vv.y + c.z * vv.z + c.w * vv.w;
    }
    s0 = warp_sum(s0);
    s1 = warp_sum(s1);
    if (l == 0) {
        gout[i0 + 2 * w]     = 1.0f / s0;
        gout[i0 + 2 * w + 1] = 1.0f / s1;
    }
}

// ---------------- fused persistent kernel ----------------
__global__ __launch_bounds__(NT) void fused_kernel(const float* __restrict__ ys,
                                                   const float* __restrict__ yt,
                                                   float* __restrict__ out) {
    extern __shared__ float sm[];
    float* sK   = sm;                         // 16*1024
    float* sKT  = sm + ROWS_S * NN;           // 16*1024
    float* sVec = sm + 2 * ROWS_S * NN;       // 1024
    float* sPS  = sVec + NN;                  // 8*64
    float* sRed = sPS + ROWS_B * CC;          // 16

    int b = blockIdx.x, t = threadIdx.x;
    unsigned R = 0;
    if (t == 0)
        asm volatile("ld.relaxed.gpu.global.u32 %0, [%1];"
                     : "=r"(R) : "l"(&g_flagA[0]) : "memory");

    // ---- Phase A: softmax over N axis for batch sample 7 (one channel/block)
    {
        const float* y = (b < CC) ? ys : yt;
        float* pT      = (b < CC) ? g_psT : g_ptT;
        int c = b & (CC - 1);
        const float* base = y + 7 * NN * CC;
        float vals[4];
        float mx = -3.4e38f;
#pragma unroll
        for (int k = 0; k < 4; k++) {
            vals[k] = base[(t + k * NT) * CC + c] * 0.5f;   // y / T, T=2
            mx = fmaxf(mx, vals[k]);
        }
        mx = block_max(mx, sRed);
        float s = 0.f;
#pragma unroll
        for (int k = 0; k < 4; k++) { vals[k] = expf(vals[k] - mx); s += vals[k]; }
        s = block_sum(s, sRed);
        float inv = 1.0f / s;
#pragma unroll
        for (int k = 0; k < 4; k++) pT[c * NN + t + k * NT] = vals[k] * inv;
    }
    gbar(0, R, b, 16);

    // ---- Phase B: 8 W/K rows per block via packed f32x2 ----
    {
        int i0b = b * ROWS_B;
        for (int idx = t; idx < ROWS_B * CC; idx += NT) {
            int i = idx >> 6, c = idx & 63;
            sPS[idx] = g_psT[c * NN + i0b + i];
        }
        __syncthreads();

        const unsigned long long SMASK = 0x8000000080000000ULL;
        const unsigned long long AMASK = 0x7FFFFFFF7FFFFFFFULL;
        unsigned long long acc0[ROWS_B], acc1[ROWS_B];
#pragma unroll
        for (int i = 0; i < ROWS_B; i++) { acc0[i] = 0ULL; acc1[i] = 0ULL; }

        int j0 = t * 4;
        for (int c = 0; c < CC; c++) {
            ulonglong2 bv = *(const ulonglong2*)&g_ptT[c * NN + j0];
            unsigned long long nb0 = bv.x ^ SMASK;
            unsigned long long nb1 = bv.y ^ SMASK;
#pragma unroll
            for (int i = 0; i < ROWS_B; i++) {
                unsigned ai = __float_as_uint(sPS[i * CC + c]);
                unsigned long long aa, d0, d1;
                asm("mov.b64 %0, {%1, %1};" : "=l"(aa) : "r"(ai));
                asm("add.rn.f32x2 %0, %1, %2;" : "=l"(d0) : "l"(aa), "l"(nb0));
                asm("add.rn.f32x2 %0, %1, %2;" : "=l"(d1) : "l"(aa), "l"(nb1));
                d0 &= AMASK;
                d1 &= AMASK;
                asm("add.rn.f32x2 %0, %0, %1;" : "+l"(acc0[i]) : "l"(d0));
                asm("add.rn.f32x2 %0, %0, %1;" : "+l"(acc1[i]) : "l"(d1));
            }
        }
#pragma unroll
        for (int i = 0; i < ROWS_B; i++) {
            unsigned x0, x1, x2, x3;
            asm("mov.b64 {%0, %1}, %2;" : "=r"(x0), "=r"(x1) : "l"(acc0[i]));
            asm("mov.b64 {%0, %1}, %2;" : "=r"(x2), "=r"(x3) : "l"(acc1[i]));
            float4 wv = make_float4(__uint_as_float(x0), __uint_as_float(x1),
                                    __uint_as_float(x2), __uint_as_float(x3));
            float4 kv = make_float4(__expf(-10.0f * wv.x), __expf(-10.0f * wv.y),
                                    __expf(-10.0f * wv.z), __expf(-10.0f * wv.w));
            *(float4*)&g_W[(size_t)(i0b + i) * NN + j0] = wv;
            *(float4*)&g_K[(size_t)(i0b + i) * NN + j0] = kv;
        }
    }
    gbar(1, R, b, 16);   // all g_K / g_W rows visible

    if (b >= NB_S) return;   // upper half done; 64 blocks carry on

    // ---- Sinkhorn setup: stage 16 K rows + 16 K^T rows into smem ----
    int i0 = b * ROWS_S;
    {
        const float4* src = (const float4*)&g_K[(size_t)i0 * NN];
        float4* dst = (float4*)sK;
#pragma unroll
        for (int k = 0; k < 16; k++) dst[t + k * NT] = src[t + k * NT];

#pragma unroll
        for (int r = 0; r < 4; r++) {
            int i = t * 4 + r;
            const float* row = &g_K[(size_t)i * NN + i0];
            float4 x0 = *(const float4*)(row);
            float4 x1 = *(const float4*)(row + 4);
            float4 x2 = *(const float4*)(row + 8);
            float4 x3 = *(const float4*)(row + 12);
            sKT[ 0 * NN + i] = x0.x; sKT[ 1 * NN + i] = x0.y;
            sKT[ 2 * NN + i] = x0.z; sKT[ 3 * NN + i] = x0.w;
            sKT[ 4 * NN + i] = x1.x; sKT[ 5 * NN + i] = x1.y;
            sKT[ 6 * NN + i] = x1.z; sKT[ 7 * NN + i] = x1.w;
            sKT[ 8 * NN + i] = x2.x; sKT[ 9 * NN + i] = x2.y;
            sKT[10 * NN + i] = x2.z; sKT[11 * NN + i] = x2.w;
            sKT[12 * NN + i] = x3.x; sKT[13 * NN + i] = x3.y;
            sKT[14 * NN + i] = x3.z; sKT[15 * NN + i] = x3.w;
        }
        __syncthreads();

        // first u-step is a plain row-sum (v == 1): u0 = 1/rowsum(sK)
        int w = t >> 5, l = t & 31;
        const float* K0 = sK + (2 * w) * NN;
        const float* K1 = K0 + NN;
        float s0 = 0.f, s1 = 0.f;
#pragma unroll
        for (int k = 0; k < 8; k++) {
            int j = (l + k * 32) * 4;
            float4 a = *(const float4*)&K0[j];
            float4 c = *(const float4*)&K1[j];
            s0 += a.x + a.y + a.z + a.w;
            s1 += c.x + c.y + c.z + c.w;
        }
        s0 = warp_sum(s0);
        s1 = warp_sum(s1);
        if (l == 0) {
            g_u[i0 + 2 * w]     = 1.0f / s0;
            g_u[i0 + 2 * w + 1] = 1.0f / s1;
        }
    }
    int slot = 2;
    gbar(slot++, R, b, 8);

    // ---- Sinkhorn iterations ----
    for (int it = 0; it < NITERS; it++) {
        halfstep(sKT, g_u, g_v, i0, sVec, t);     // v = 1/(K^T u)
        gbar(slot++, R, b, 8);
        if (it < NITERS - 1) {
            halfstep(sK, g_v, g_u, i0, sVec, t);  // u = 1/(K v)
            gbar(slot++, R, b, 8);
        }
    }

    // ---- loss = sum_ij u_i K_ij v_j W_ij ----
    {
        ((float4*)sVec)[t] = ((const float4*)g_v)[t];
        __syncthreads();
        int w = t >> 5, l = t & 31;
        float u0 = g_u[i0 + 2 * w];
        float u1 = g_u[i0 + 2 * w + 1];
        const float* K0 = sK + (2 * w) * NN;
        const float* K1 = K0 + NN;
        const float* W0 = g_W + (size_t)(i0 + 2 * w) * NN;
        const float* W1 = W0 + NN;
        float s0 = 0.f, s1 = 0.f;
#pragma unroll
        for (int k = 0; k < 8; k++) {
            int j = (l + k * 32) * 4;
            float4 vv = *(const float4*)&sVec[j];
            float4 a  = *(const float4*)&K0[j];
            float4 wa = *(const float4*)&W0[j];
            float4 c  = *(const float4*)&K1[j];
            float4 wc = *(const float4*)&W1[j];
            s0 += a.x * wa.x * vv.x + a.y * wa.y * vv.y
                + a.z * wa.z * vv.z + a.w * wa.w * vv.w;
            s1 += c.x * wc.x * vv.x + c.y * wc.y * vv.y
                + c.z * wc.z * vv.z + c.w * wc.w * vv.w;
        }
        s0 = warp_sum(s0) * u0;
        s1 = warp_sum(s1) * u1;
        if (l == 0) sRed[w] = s0 + s1;
        __syncthreads();
        if (t == 0) {
            float tot = 0.f;
#pragma unroll
            for (int i = 0; i < 8; i++) tot += sRed[i];
            g_partial[b] = tot;
        }
    }
    gbar(slot++, R, b, 8);

    if (b == 0) {
        float v = (t < NB_S) ? g_partial[t] : 0.f;
        v = block_sum(v, sRed);
        if (t == 0) out[0] = LSCALE * v;
    }
}

#define SMEM_BYTES ((2 * ROWS_S * NN + NN + ROWS_B * CC + 16) * (int)sizeof(float))

extern "C" void kernel_launch(void* const* d_in, const int* in_sizes, int n_in,
                              void* d_out, int out_size) {
    const float* ys = (const float*)d_in[0];
    const float* yt = (const float*)d_in[1];
    cudaFuncSetAttribute(fused_kernel, cudaFuncAttributeMaxDynamicSharedMemorySize,
                         SMEM_BYTES);
    fused_kernel<<<NB_ALL, NT, SMEM_BYTES>>>(ys, yt, (float*)d_out);
}